// round 2
// baseline (speedup 1.0000x reference)
#include <cuda_runtime.h>
#include <math_constants.h>

// ProbabilisticChamferDistanceLoss — d^2 min (sqrt deferred), smem-tiled,
// packed f32x2 math (sm_103a), 2 queries/thread, deterministic reduction.

#define N_ORIG 30000
#define M_SIMP 10000

#define JTILE  2500     // Ps tile per block in kern_os
#define JSPLIT 4        // 10000 / 2500
#define JPAIRS (JTILE / 2)
#define ITILE  3000     // P tile per block in kern_so
#define ISPLIT 10       // 30000 / 3000
#define IPAIRS (ITILE / 2)

typedef unsigned long long ull;

// ---- packed f32x2 helpers (sm_103a) ----
__device__ __forceinline__ ull f2_add(ull a, ull b) {
    ull r; asm("add.rn.f32x2 %0, %1, %2;" : "=l"(r) : "l"(a), "l"(b)); return r;
}
__device__ __forceinline__ ull f2_mul(ull a, ull b) {
    ull r; asm("mul.rn.f32x2 %0, %1, %2;" : "=l"(r) : "l"(a), "l"(b)); return r;
}
__device__ __forceinline__ ull f2_fma(ull a, ull b, ull c) {
    ull r; asm("fma.rn.f32x2 %0, %1, %2, %3;" : "=l"(r) : "l"(a), "l"(b), "l"(c)); return r;
}
__device__ __forceinline__ ull f2_bcast(float v) {
    ull r; unsigned u = __float_as_uint(v);
    asm("mov.b64 %0, {%1, %1};" : "=l"(r) : "r"(u)); return r;
}
__device__ __forceinline__ void f2_unpack(float& lo, float& hi, ull v) {
    unsigned a, b;
    asm("mov.b64 {%0, %1}, %2;" : "=r"(a), "=r"(b) : "l"(v));
    lo = __uint_as_float(a); hi = __uint_as_float(b);
}

// Scratch (device globals — no allocation allowed)
__device__ float g_os_d2[JSPLIT * N_ORIG];
__device__ int   g_os_j [JSPLIT * N_ORIG];
__device__ float g_so_d2[ISPLIT * M_SIMP];
__device__ float g_part[256];

// ---------------------------------------------------------------------------
// o -> s: per original point i, min_j d^2 + argmin over one JTILE chunk.
// grid: (ceil(N/512), JSPLIT), 256 threads, 2 queries/thread.
// smem tile: pair-interleaved  sxy[k]=(x0,x1,y0,y1)  sz[k]=(z0,z1)
// ---------------------------------------------------------------------------
__global__ __launch_bounds__(256) void kern_os(const float* __restrict__ P,
                                               const float* __restrict__ Ps) {
    __shared__ float4 sxy[JPAIRS];
    __shared__ ull    sz [JPAIRS];
    const int tid = threadIdx.x;
    const int jbase = blockIdx.y * JTILE;

    for (int k = tid; k < JPAIRS; k += 256) {
        const int j0 = jbase + 2 * k;
        float x0 = Ps[3 * j0],     y0 = Ps[3 * j0 + 1], z0 = Ps[3 * j0 + 2];
        float x1 = Ps[3 * j0 + 3], y1 = Ps[3 * j0 + 4], z1 = Ps[3 * j0 + 5];
        sxy[k] = make_float4(x0, x1, y0, y1);
        ull zz; unsigned u0 = __float_as_uint(z0), u1 = __float_as_uint(z1);
        asm("mov.b64 %0, {%1, %2};" : "=l"(zz) : "r"(u0), "r"(u1));
        sz[k] = zz;
    }
    __syncthreads();

    const int i0 = blockIdx.x * 512 + tid;
    const int i1 = i0 + 256;
    const bool v0 = (i0 < N_ORIG), v1 = (i1 < N_ORIG);
    const int r0 = v0 ? i0 : 0, r1 = v1 ? i1 : 0;

    const ull npx0 = f2_bcast(-P[3 * r0]), npy0 = f2_bcast(-P[3 * r0 + 1]), npz0 = f2_bcast(-P[3 * r0 + 2]);
    const ull npx1 = f2_bcast(-P[3 * r1]), npy1 = f2_bcast(-P[3 * r1 + 1]), npz1 = f2_bcast(-P[3 * r1 + 2]);

    float bA0 = CUDART_INF_F, bB0 = CUDART_INF_F, bA1 = CUDART_INF_F, bB1 = CUDART_INF_F;
    int kA0 = 0, kB0 = 0, kA1 = 0, kB1 = 0;

#pragma unroll 5
    for (int k = 0; k < JPAIRS; ++k) {
        const float4 xy = sxy[k];
        ull x01, y01;
        {
            unsigned a = __float_as_uint(xy.x), b = __float_as_uint(xy.y);
            asm("mov.b64 %0, {%1, %2};" : "=l"(x01) : "r"(a), "r"(b));
            unsigned c = __float_as_uint(xy.z), d = __float_as_uint(xy.w);
            asm("mov.b64 %0, {%1, %2};" : "=l"(y01) : "r"(c), "r"(d));
        }
        const ull z01 = sz[k];

        // query 0
        {
            ull dx = f2_add(x01, npx0), dy = f2_add(y01, npy0), dz = f2_add(z01, npz0);
            ull t = f2_mul(dz, dz); t = f2_fma(dy, dy, t); t = f2_fma(dx, dx, t);
            float d0, d1; f2_unpack(d0, d1, t);
            if (d0 < bA0) { bA0 = d0; kA0 = k; }
            if (d1 < bB0) { bB0 = d1; kB0 = k; }
        }
        // query 1
        {
            ull dx = f2_add(x01, npx1), dy = f2_add(y01, npy1), dz = f2_add(z01, npz1);
            ull t = f2_mul(dz, dz); t = f2_fma(dy, dy, t); t = f2_fma(dx, dx, t);
            float d0, d1; f2_unpack(d0, d1, t);
            if (d0 < bA1) { bA1 = d0; kA1 = k; }
            if (d1 < bB1) { bB1 = d1; kB1 = k; }
        }
    }

    if (v0) {
        float best = bA0; int bj = 2 * kA0;
        if (bB0 < bA0) { best = bB0; bj = 2 * kB0 + 1; }
        g_os_d2[blockIdx.y * N_ORIG + i0] = best;
        g_os_j [blockIdx.y * N_ORIG + i0] = jbase + bj;
    }
    if (v1) {
        float best = bA1; int bj = 2 * kA1;
        if (bB1 < bA1) { best = bB1; bj = 2 * kB1 + 1; }
        g_os_d2[blockIdx.y * N_ORIG + i1] = best;
        g_os_j [blockIdx.y * N_ORIG + i1] = jbase + bj;
    }
}

// ---------------------------------------------------------------------------
// s -> o: per simplified point j, min_i d^2 over one ITILE chunk (no argmin).
// grid: (ceil(M/512), ISPLIT), 256 threads, 2 queries/thread.
// ---------------------------------------------------------------------------
__global__ __launch_bounds__(256) void kern_so(const float* __restrict__ Ps,
                                               const float* __restrict__ P) {
    __shared__ float4 sxy[IPAIRS];
    __shared__ ull    sz [IPAIRS];
    const int tid = threadIdx.x;
    const int ibase = blockIdx.y * ITILE;

    for (int k = tid; k < IPAIRS; k += 256) {
        const int i0 = ibase + 2 * k;
        float x0 = P[3 * i0],     y0 = P[3 * i0 + 1], z0 = P[3 * i0 + 2];
        float x1 = P[3 * i0 + 3], y1 = P[3 * i0 + 4], z1 = P[3 * i0 + 5];
        sxy[k] = make_float4(x0, x1, y0, y1);
        ull zz; unsigned u0 = __float_as_uint(z0), u1 = __float_as_uint(z1);
        asm("mov.b64 %0, {%1, %2};" : "=l"(zz) : "r"(u0), "r"(u1));
        sz[k] = zz;
    }
    __syncthreads();

    const int j0 = blockIdx.x * 512 + tid;
    const int j1 = j0 + 256;
    const bool v0 = (j0 < M_SIMP), v1 = (j1 < M_SIMP);
    const int r0 = v0 ? j0 : 0, r1 = v1 ? j1 : 0;

    const ull nqx0 = f2_bcast(-Ps[3 * r0]), nqy0 = f2_bcast(-Ps[3 * r0 + 1]), nqz0 = f2_bcast(-Ps[3 * r0 + 2]);
    const ull nqx1 = f2_bcast(-Ps[3 * r1]), nqy1 = f2_bcast(-Ps[3 * r1 + 1]), nqz1 = f2_bcast(-Ps[3 * r1 + 2]);

    float bA0 = CUDART_INF_F, bB0 = CUDART_INF_F, bA1 = CUDART_INF_F, bB1 = CUDART_INF_F;

#pragma unroll 5
    for (int k = 0; k < IPAIRS; ++k) {
        const float4 xy = sxy[k];
        ull x01, y01;
        {
            unsigned a = __float_as_uint(xy.x), b = __float_as_uint(xy.y);
            asm("mov.b64 %0, {%1, %2};" : "=l"(x01) : "r"(a), "r"(b));
            unsigned c = __float_as_uint(xy.z), d = __float_as_uint(xy.w);
            asm("mov.b64 %0, {%1, %2};" : "=l"(y01) : "r"(c), "r"(d));
        }
        const ull z01 = sz[k];

        {
            ull dx = f2_add(x01, nqx0), dy = f2_add(y01, nqy0), dz = f2_add(z01, nqz0);
            ull t = f2_mul(dz, dz); t = f2_fma(dy, dy, t); t = f2_fma(dx, dx, t);
            float d0, d1; f2_unpack(d0, d1, t);
            bA0 = fminf(bA0, d0); bB0 = fminf(bB0, d1);
        }
        {
            ull dx = f2_add(x01, nqx1), dy = f2_add(y01, nqy1), dz = f2_add(z01, nqz1);
            ull t = f2_mul(dz, dz); t = f2_fma(dy, dy, t); t = f2_fma(dx, dx, t);
            float d0, d1; f2_unpack(d0, d1, t);
            bA1 = fminf(bA1, d0); bB1 = fminf(bB1, d1);
        }
    }

    if (v0) g_so_d2[blockIdx.y * M_SIMP + j0] = fminf(bA0, bB0);
    if (v1) g_so_d2[blockIdx.y * M_SIMP + j1] = fminf(bA1, bB1);
}

// ---------------------------------------------------------------------------
// Combine split partials, apply sqrt + probability weights, per-block sums.
// ---------------------------------------------------------------------------
__global__ __launch_bounds__(256) void kern_reduce(const float* __restrict__ prob) {
    __shared__ float red[256];
    const int idx = blockIdx.x * 256 + threadIdx.x;

    float local = 0.0f;
    if (idx < N_ORIG) {
        float best = g_os_d2[idx];
        int bj = g_os_j[idx];
#pragma unroll
        for (int sp = 1; sp < JSPLIT; ++sp) {
            const float v = g_os_d2[sp * N_ORIG + idx];
            if (v < best) { best = v; bj = g_os_j[sp * N_ORIG + idx]; }
        }
        local = sqrtf(best) * prob[bj];
    } else if (idx < N_ORIG + M_SIMP) {
        const int j = idx - N_ORIG;
        float best = g_so_d2[j];
#pragma unroll
        for (int sp = 1; sp < ISPLIT; ++sp)
            best = fminf(best, g_so_d2[sp * M_SIMP + j]);
        local = sqrtf(best) * prob[j];
    }

    red[threadIdx.x] = local;
    __syncthreads();
#pragma unroll
    for (int off = 128; off > 0; off >>= 1) {
        if (threadIdx.x < off) red[threadIdx.x] += red[threadIdx.x + off];
        __syncthreads();
    }
    if (threadIdx.x == 0) g_part[blockIdx.x] = red[0];
}

__global__ __launch_bounds__(256) void kern_final(float* __restrict__ out, int nblocks) {
    __shared__ float red[256];
    red[threadIdx.x] = (threadIdx.x < nblocks) ? g_part[threadIdx.x] : 0.0f;
    __syncthreads();
#pragma unroll
    for (int off = 128; off > 0; off >>= 1) {
        if (threadIdx.x < off) red[threadIdx.x] += red[threadIdx.x + off];
        __syncthreads();
    }
    if (threadIdx.x == 0) out[0] = red[0];
}

extern "C" void kernel_launch(void* const* d_in, const int* in_sizes, int n_in,
                              void* d_out, int out_size) {
    const float* P    = (const float*)d_in[0];   // (N, 3)
    const float* Ps   = (const float*)d_in[1];   // (M, 3)
    const float* prob = (const float*)d_in[2];   // (M,)
    float* out = (float*)d_out;

    dim3 gA((N_ORIG + 511) / 512, JSPLIT);   // 59 x 4
    kern_os<<<gA, 256>>>(P, Ps);

    dim3 gB((M_SIMP + 511) / 512, ISPLIT);   // 20 x 10
    kern_so<<<gB, 256>>>(Ps, P);

    const int RB = (N_ORIG + M_SIMP + 255) / 256;  // 157
    kern_reduce<<<RB, 256>>>(prob);
    kern_final<<<1, 256>>>(out, RB);
}

// round 3
// speedup vs baseline: 1.4330x; 1.4330x over previous
#include <cuda_runtime.h>
#include <math_constants.h>

// ProbabilisticChamferDistanceLoss — dot-product form (s = |q|^2 - 2 p.q, matches
// reference), packed f32x2 FFMA, fused os+so kernel, counter-folded final reduce.

#define N_ORIG 30000
#define M_SIMP 10000

#define JTILE  2500           // Ps tile (os part)
#define JSPLIT 4
#define JPAIRS (JTILE / 2)    // 1250
#define OSX    ((N_ORIG + 511) / 512)      // 59 blocks per split
#define OS_BLOCKS (OSX * JSPLIT)           // 236

#define ITILE  3000           // P tile (so part)
#define ISPLIT 10
#define IPAIRS (ITILE / 2)    // 1500
#define SOX    ((M_SIMP + 511) / 512)      // 20 blocks per split
#define SO_BLOCKS (SOX * ISPLIT)           // 200

#define TOTAL_BLOCKS (OS_BLOCKS + SO_BLOCKS)   // 436

typedef unsigned long long ull;

// ---- packed f32x2 helpers (sm_103a) ----
__device__ __forceinline__ ull f2_fma(ull a, ull b, ull c) {
    ull r; asm("fma.rn.f32x2 %0, %1, %2, %3;" : "=l"(r) : "l"(a), "l"(b), "l"(c)); return r;
}
__device__ __forceinline__ ull f2_bcast(float v) {
    ull r; unsigned u = __float_as_uint(v);
    asm("mov.b64 %0, {%1, %1};" : "=l"(r) : "r"(u)); return r;
}
__device__ __forceinline__ ull f2_pack(float a, float b) {
    ull r; unsigned ua = __float_as_uint(a), ub = __float_as_uint(b);
    asm("mov.b64 %0, {%1, %2};" : "=l"(r) : "r"(ua), "r"(ub)); return r;
}
__device__ __forceinline__ void f2_unpack(float& lo, float& hi, ull v) {
    unsigned a, b;
    asm("mov.b64 {%0, %1}, %2;" : "=r"(a), "=r"(b) : "l"(v));
    lo = __uint_as_float(a); hi = __uint_as_float(b);
}

// Scratch (device globals — no allocation allowed)
__device__ float g_os_d2[JSPLIT * N_ORIG];
__device__ int   g_os_j [JSPLIT * N_ORIG];
__device__ float g_so_d2[ISPLIT * M_SIMP];
__device__ float g_part[256];
__device__ int   g_count;

// ---------------------------------------------------------------------------
// Fused main kernel: blocks [0, OS_BLOCKS) do o->s, rest do s->o.
// Tile layout (pair-interleaved):
//   sxy[k] = (x0, x1, y0, y1)     szc[k] = (z0, z1, c0, c1)   c = |pt|^2
// Inner step per 2 tile points per query: 3 packed FFMA, then min/argmin.
// ---------------------------------------------------------------------------
__global__ __launch_bounds__(256) void kern_main(const float* __restrict__ P,
                                                 const float* __restrict__ Ps) {
    __shared__ float4 sxy[IPAIRS];   // sized for the larger (so) tile
    __shared__ float4 szc[IPAIRS];

    const int tid = threadIdx.x;
    const int b = blockIdx.x;

    if (b < OS_BLOCKS) {
        // ---------------- o -> s ----------------
        const int bx = b % OSX;
        const int by = b / OSX;
        const int jbase = by * JTILE;

        for (int k = tid; k < JPAIRS; k += 256) {
            const int j0 = jbase + 2 * k;
            const float x0 = Ps[3 * j0],     y0 = Ps[3 * j0 + 1], z0 = Ps[3 * j0 + 2];
            const float x1 = Ps[3 * j0 + 3], y1 = Ps[3 * j0 + 4], z1 = Ps[3 * j0 + 5];
            sxy[k] = make_float4(x0, x1, y0, y1);
            const float c0 = fmaf(x0, x0, fmaf(y0, y0, z0 * z0));
            const float c1 = fmaf(x1, x1, fmaf(y1, y1, z1 * z1));
            szc[k] = make_float4(z0, z1, c0, c1);
        }
        __syncthreads();

        const int i0 = bx * 512 + tid;
        const int i1 = i0 + 256;
        const bool v0 = (i0 < N_ORIG), v1 = (i1 < N_ORIG);
        const int r0 = v0 ? i0 : 0, r1 = v1 ? i1 : 0;

        const float p0x = P[3 * r0], p0y = P[3 * r0 + 1], p0z = P[3 * r0 + 2];
        const float p1x = P[3 * r1], p1y = P[3 * r1 + 1], p1z = P[3 * r1 + 2];
        const ull m0x = f2_bcast(-2.0f * p0x), m0y = f2_bcast(-2.0f * p0y), m0z = f2_bcast(-2.0f * p0z);
        const ull m1x = f2_bcast(-2.0f * p1x), m1y = f2_bcast(-2.0f * p1y), m1z = f2_bcast(-2.0f * p1z);
        const float p0sq = fmaf(p0x, p0x, fmaf(p0y, p0y, p0z * p0z));
        const float p1sq = fmaf(p1x, p1x, fmaf(p1y, p1y, p1z * p1z));

        float bA0 = CUDART_INF_F, bB0 = CUDART_INF_F, bA1 = CUDART_INF_F, bB1 = CUDART_INF_F;
        int kA0 = 0, kB0 = 0, kA1 = 0, kB1 = 0;

#pragma unroll 5
        for (int k = 0; k < JPAIRS; ++k) {
            const float4 a = sxy[k];
            const float4 zc = szc[k];
            const ull x01 = f2_pack(a.x, a.y);
            const ull y01 = f2_pack(a.z, a.w);
            const ull z01 = f2_pack(zc.x, zc.y);
            const ull c01 = f2_pack(zc.z, zc.w);

            {   // query 0: s = c - 2 p.q
                ull t = f2_fma(m0z, z01, c01);
                t = f2_fma(m0y, y01, t);
                t = f2_fma(m0x, x01, t);
                float d0, d1; f2_unpack(d0, d1, t);
                if (d0 < bA0) { bA0 = d0; kA0 = k; }
                if (d1 < bB0) { bB0 = d1; kB0 = k; }
            }
            {   // query 1
                ull t = f2_fma(m1z, z01, c01);
                t = f2_fma(m1y, y01, t);
                t = f2_fma(m1x, x01, t);
                float d0, d1; f2_unpack(d0, d1, t);
                if (d0 < bA1) { bA1 = d0; kA1 = k; }
                if (d1 < bB1) { bB1 = d1; kB1 = k; }
            }
        }

        if (v0) {
            float best = bA0; int bj = 2 * kA0;
            if (bB0 < bA0) { best = bB0; bj = 2 * kB0 + 1; }
            g_os_d2[by * N_ORIG + i0] = best + p0sq;     // = d^2 (may be ~-eps)
            g_os_j [by * N_ORIG + i0] = jbase + bj;
        }
        if (v1) {
            float best = bA1; int bj = 2 * kA1;
            if (bB1 < bA1) { best = bB1; bj = 2 * kB1 + 1; }
            g_os_d2[by * N_ORIG + i1] = best + p1sq;
            g_os_j [by * N_ORIG + i1] = jbase + bj;
        }
    } else {
        // ---------------- s -> o ----------------
        const int bb = b - OS_BLOCKS;
        const int bx = bb % SOX;
        const int by = bb / SOX;
        const int ibase = by * ITILE;

        for (int k = tid; k < IPAIRS; k += 256) {
            const int i0 = ibase + 2 * k;
            const float x0 = P[3 * i0],     y0 = P[3 * i0 + 1], z0 = P[3 * i0 + 2];
            const float x1 = P[3 * i0 + 3], y1 = P[3 * i0 + 4], z1 = P[3 * i0 + 5];
            sxy[k] = make_float4(x0, x1, y0, y1);
            const float c0 = fmaf(x0, x0, fmaf(y0, y0, z0 * z0));
            const float c1 = fmaf(x1, x1, fmaf(y1, y1, z1 * z1));
            szc[k] = make_float4(z0, z1, c0, c1);
        }
        __syncthreads();

        const int j0 = bx * 512 + tid;
        const int j1 = j0 + 256;
        const bool v0 = (j0 < M_SIMP), v1 = (j1 < M_SIMP);
        const int r0 = v0 ? j0 : 0, r1 = v1 ? j1 : 0;

        const float q0x = Ps[3 * r0], q0y = Ps[3 * r0 + 1], q0z = Ps[3 * r0 + 2];
        const float q1x = Ps[3 * r1], q1y = Ps[3 * r1 + 1], q1z = Ps[3 * r1 + 2];
        const ull m0x = f2_bcast(-2.0f * q0x), m0y = f2_bcast(-2.0f * q0y), m0z = f2_bcast(-2.0f * q0z);
        const ull m1x = f2_bcast(-2.0f * q1x), m1y = f2_bcast(-2.0f * q1y), m1z = f2_bcast(-2.0f * q1z);
        const float q0sq = fmaf(q0x, q0x, fmaf(q0y, q0y, q0z * q0z));
        const float q1sq = fmaf(q1x, q1x, fmaf(q1y, q1y, q1z * q1z));

        float bA0 = CUDART_INF_F, bB0 = CUDART_INF_F, bA1 = CUDART_INF_F, bB1 = CUDART_INF_F;

#pragma unroll 5
        for (int k = 0; k < IPAIRS; ++k) {
            const float4 a = sxy[k];
            const float4 zc = szc[k];
            const ull x01 = f2_pack(a.x, a.y);
            const ull y01 = f2_pack(a.z, a.w);
            const ull z01 = f2_pack(zc.x, zc.y);
            const ull c01 = f2_pack(zc.z, zc.w);

            {
                ull t = f2_fma(m0z, z01, c01);
                t = f2_fma(m0y, y01, t);
                t = f2_fma(m0x, x01, t);
                float d0, d1; f2_unpack(d0, d1, t);
                bA0 = fminf(bA0, d0); bB0 = fminf(bB0, d1);
            }
            {
                ull t = f2_fma(m1z, z01, c01);
                t = f2_fma(m1y, y01, t);
                t = f2_fma(m1x, x01, t);
                float d0, d1; f2_unpack(d0, d1, t);
                bA1 = fminf(bA1, d0); bB1 = fminf(bB1, d1);
            }
        }

        if (v0) g_so_d2[by * M_SIMP + j0] = fminf(bA0, bB0) + q0sq;
        if (v1) g_so_d2[by * M_SIMP + j1] = fminf(bA1, bB1) + q1sq;
    }
}

// ---------------------------------------------------------------------------
// Reduce: combine split partials, sqrt + probability weights, per-block sums;
// the last block (deterministic counter) sums g_part in fixed order -> out.
// ---------------------------------------------------------------------------
#define RB ((N_ORIG + M_SIMP + 255) / 256)   // 157

__global__ __launch_bounds__(256) void kern_reduce(const float* __restrict__ prob,
                                                   float* __restrict__ out) {
    __shared__ float red[256];
    const int idx = blockIdx.x * 256 + threadIdx.x;

    float local = 0.0f;
    if (idx < N_ORIG) {
        float best = g_os_d2[idx];
        int bj = g_os_j[idx];
#pragma unroll
        for (int sp = 1; sp < JSPLIT; ++sp) {
            const float v = g_os_d2[sp * N_ORIG + idx];
            if (v < best) { best = v; bj = g_os_j[sp * N_ORIG + idx]; }
        }
        local = sqrtf(fmaxf(best, 0.0f)) * prob[bj];
    } else if (idx < N_ORIG + M_SIMP) {
        const int j = idx - N_ORIG;
        float best = g_so_d2[j];
#pragma unroll
        for (int sp = 1; sp < ISPLIT; ++sp)
            best = fminf(best, g_so_d2[sp * M_SIMP + j]);
        local = sqrtf(fmaxf(best, 0.0f)) * prob[j];
    }

    red[threadIdx.x] = local;
    __syncthreads();
#pragma unroll
    for (int off = 128; off > 0; off >>= 1) {
        if (threadIdx.x < off) red[threadIdx.x] += red[threadIdx.x + off];
        __syncthreads();
    }

    __shared__ bool amLast;
    if (threadIdx.x == 0) {
        g_part[blockIdx.x] = red[0];
        __threadfence();
        amLast = (atomicAdd(&g_count, 1) == gridDim.x - 1);
    }
    __syncthreads();

    if (amLast) {
        // fixed-order final sum (deterministic)
        float v = (threadIdx.x < RB) ? __ldcg(&g_part[threadIdx.x]) : 0.0f;
        red[threadIdx.x] = v;
        __syncthreads();
#pragma unroll
        for (int off = 128; off > 0; off >>= 1) {
            if (threadIdx.x < off) red[threadIdx.x] += red[threadIdx.x + off];
            __syncthreads();
        }
        if (threadIdx.x == 0) {
            out[0] = red[0];
            g_count = 0;     // reset for next graph replay
        }
    }
}

extern "C" void kernel_launch(void* const* d_in, const int* in_sizes, int n_in,
                              void* d_out, int out_size) {
    const float* P    = (const float*)d_in[0];   // (N, 3)
    const float* Ps   = (const float*)d_in[1];   // (M, 3)
    const float* prob = (const float*)d_in[2];   // (M,)
    float* out = (float*)d_out;

    kern_main<<<TOTAL_BLOCKS, 256>>>(P, Ps);
    kern_reduce<<<RB, 256>>>(prob, out);
}

// round 8
// speedup vs baseline: 2.0419x; 1.4249x over previous
#include <cuda_runtime.h>
#include <math_constants.h>

// ProbabilisticChamferDistanceLoss — dot-product form (s = |q|^2 - 2 p.q),
// packed f32x2 FFMA, group-of-4 tree-min with deferred exact argmin,
// fused os+so kernel, counter-folded deterministic final reduce.

#define N_ORIG 30000
#define M_SIMP 10000

#define JTILE  2500           // Ps tile (os part)
#define JSPLIT 4
#define JPAIRS (JTILE / 2)    // 1250
#define JGROUPS (JTILE / 4)   // 625
#define OSX    ((N_ORIG + 511) / 512)      // 59
#define OS_BLOCKS (OSX * JSPLIT)           // 236

#define ITILE  3000           // P tile (so part)
#define ISPLIT 10
#define IPAIRS (ITILE / 2)    // 1500
#define IGROUPS (ITILE / 4)   // 750
#define SOX    ((M_SIMP + 511) / 512)      // 20
#define SO_BLOCKS (SOX * ISPLIT)           // 200

#define TOTAL_BLOCKS (OS_BLOCKS + SO_BLOCKS)   // 436

typedef unsigned long long ull;

// ---- packed f32x2 helpers (sm_103a) ----
__device__ __forceinline__ ull f2_fma(ull a, ull b, ull c) {
    ull r; asm("fma.rn.f32x2 %0, %1, %2, %3;" : "=l"(r) : "l"(a), "l"(b), "l"(c)); return r;
}
__device__ __forceinline__ ull f2_bcast(float v) {
    ull r; unsigned u = __float_as_uint(v);
    asm("mov.b64 %0, {%1, %1};" : "=l"(r) : "r"(u)); return r;
}
__device__ __forceinline__ ull f2_pack(float a, float b) {
    ull r; unsigned ua = __float_as_uint(a), ub = __float_as_uint(b);
    asm("mov.b64 %0, {%1, %2};" : "=l"(r) : "r"(ua), "r"(ub)); return r;
}
__device__ __forceinline__ void f2_unpack(float& lo, float& hi, ull v) {
    unsigned a, b;
    asm("mov.b64 {%0, %1}, %2;" : "=r"(a), "=r"(b) : "l"(v));
    lo = __uint_as_float(a); hi = __uint_as_float(b);
}

// Scratch (device globals)
__device__ float g_os_d2[JSPLIT * N_ORIG];
__device__ int   g_os_j [JSPLIT * N_ORIG];
__device__ float g_so_d2[ISPLIT * M_SIMP];
__device__ float g_part[384];
__device__ int   g_count;

// Compute the packed distances for one group (2 packed pairs) vs one query.
__device__ __forceinline__ void group_dists(const float4& aA, const float4& zA,
                                            const float4& aB, const float4& zB,
                                            ull mx, ull my, ull mz,
                                            float& a0, float& a1, float& b0, float& b1) {
    const ull xA = f2_pack(aA.x, aA.y), yA = f2_pack(aA.z, aA.w);
    const ull zzA = f2_pack(zA.x, zA.y), cA = f2_pack(zA.z, zA.w);
    const ull xB = f2_pack(aB.x, aB.y), yB = f2_pack(aB.z, aB.w);
    const ull zzB = f2_pack(zB.x, zB.y), cB = f2_pack(zB.z, zB.w);
    ull tA = f2_fma(mz, zzA, cA); tA = f2_fma(my, yA, tA); tA = f2_fma(mx, xA, tA);
    ull tB = f2_fma(mz, zzB, cB); tB = f2_fma(my, yB, tB); tB = f2_fma(mx, xB, tB);
    f2_unpack(a0, a1, tA);
    f2_unpack(b0, b1, tB);
}

// ---------------------------------------------------------------------------
// Fused main kernel: blocks [0, OS_BLOCKS) do o->s (min+argmin), rest s->o (min).
// Tile: sxy[k]=(x0,x1,y0,y1)  szc[k]=(z0,z1,c0,c1), c=|pt|^2, pair-interleaved.
// ---------------------------------------------------------------------------
__global__ __launch_bounds__(256) void kern_main(const float* __restrict__ P,
                                                 const float* __restrict__ Ps) {
    __shared__ float4 sxy[IPAIRS];   // sized for the larger (so) tile
    __shared__ float4 szc[IPAIRS];

    const int tid = threadIdx.x;
    const int b = blockIdx.x;

    if (b < OS_BLOCKS) {
        // ---------------- o -> s ----------------
        const int bx = b % OSX;
        const int by = b / OSX;
        const int jbase = by * JTILE;

        for (int k = tid; k < JPAIRS; k += 256) {
            const int j0 = jbase + 2 * k;
            const float x0 = Ps[3 * j0],     y0 = Ps[3 * j0 + 1], z0 = Ps[3 * j0 + 2];
            const float x1 = Ps[3 * j0 + 3], y1 = Ps[3 * j0 + 4], z1 = Ps[3 * j0 + 5];
            sxy[k] = make_float4(x0, x1, y0, y1);
            const float c0 = fmaf(x0, x0, fmaf(y0, y0, z0 * z0));
            const float c1 = fmaf(x1, x1, fmaf(y1, y1, z1 * z1));
            szc[k] = make_float4(z0, z1, c0, c1);
        }
        __syncthreads();

        const int i0 = bx * 512 + tid;
        const int i1 = i0 + 256;
        const bool v0 = (i0 < N_ORIG), v1 = (i1 < N_ORIG);
        const int r0 = v0 ? i0 : 0, r1 = v1 ? i1 : 0;

        const float p0x = P[3 * r0], p0y = P[3 * r0 + 1], p0z = P[3 * r0 + 2];
        const float p1x = P[3 * r1], p1y = P[3 * r1 + 1], p1z = P[3 * r1 + 2];
        const ull m0x = f2_bcast(-2.0f * p0x), m0y = f2_bcast(-2.0f * p0y), m0z = f2_bcast(-2.0f * p0z);
        const ull m1x = f2_bcast(-2.0f * p1x), m1y = f2_bcast(-2.0f * p1y), m1z = f2_bcast(-2.0f * p1z);
        const float p0sq = fmaf(p0x, p0x, fmaf(p0y, p0y, p0z * p0z));
        const float p1sq = fmaf(p1x, p1x, fmaf(p1y, p1y, p1z * p1z));

        float best0 = CUDART_INF_F, best1 = CUDART_INF_F;
        int bg0 = 0, bg1 = 0;

#pragma unroll 5
        for (int g = 0; g < JGROUPS; ++g) {
            const float4 aA = sxy[2 * g],     zA = szc[2 * g];
            const float4 aB = sxy[2 * g + 1], zB = szc[2 * g + 1];
            {
                float a0, a1, c0, c1;
                group_dists(aA, zA, aB, zB, m0x, m0y, m0z, a0, a1, c0, c1);
                const float m = fminf(fminf(a0, a1), fminf(c0, c1));
                if (m < best0) { best0 = m; bg0 = g; }   // strict < => earliest group
            }
            {
                float a0, a1, c0, c1;
                group_dists(aA, zA, aB, zB, m1x, m1y, m1z, a0, a1, c0, c1);
                const float m = fminf(fminf(a0, a1), fminf(c0, c1));
                if (m < best1) { best1 = m; bg1 = g; }
            }
        }

        // Deferred exact argmin: recompute winning group (bitwise identical),
        // first-occurrence tie-break within the group.
        if (v0) {
            const int g = bg0;
            float a0, a1, c0, c1;
            group_dists(sxy[2 * g], szc[2 * g], sxy[2 * g + 1], szc[2 * g + 1],
                        m0x, m0y, m0z, a0, a1, c0, c1);
            int off = 3;
            if (c0 == best0) off = 2;
            if (a1 == best0) off = 1;
            if (a0 == best0) off = 0;
            g_os_d2[by * N_ORIG + i0] = best0 + p0sq;
            g_os_j [by * N_ORIG + i0] = jbase + 4 * g + off;
        }
        if (v1) {
            const int g = bg1;
            float a0, a1, c0, c1;
            group_dists(sxy[2 * g], szc[2 * g], sxy[2 * g + 1], szc[2 * g + 1],
                        m1x, m1y, m1z, a0, a1, c0, c1);
            int off = 3;
            if (c0 == best1) off = 2;
            if (a1 == best1) off = 1;
            if (a0 == best1) off = 0;
            g_os_d2[by * N_ORIG + i1] = best1 + p1sq;
            g_os_j [by * N_ORIG + i1] = jbase + 4 * g + off;
        }
    } else {
        // ---------------- s -> o ----------------
        const int bb = b - OS_BLOCKS;
        const int bx = bb % SOX;
        const int by = bb / SOX;
        const int ibase = by * ITILE;

        for (int k = tid; k < IPAIRS; k += 256) {
            const int i0 = ibase + 2 * k;
            const float x0 = P[3 * i0],     y0 = P[3 * i0 + 1], z0 = P[3 * i0 + 2];
            const float x1 = P[3 * i0 + 3], y1 = P[3 * i0 + 4], z1 = P[3 * i0 + 5];
            sxy[k] = make_float4(x0, x1, y0, y1);
            const float c0 = fmaf(x0, x0, fmaf(y0, y0, z0 * z0));
            const float c1 = fmaf(x1, x1, fmaf(y1, y1, z1 * z1));
            szc[k] = make_float4(z0, z1, c0, c1);
        }
        __syncthreads();

        const int j0 = bx * 512 + tid;
        const int j1 = j0 + 256;
        const bool v0 = (j0 < M_SIMP), v1 = (j1 < M_SIMP);
        const int r0 = v0 ? j0 : 0, r1 = v1 ? j1 : 0;

        const float q0x = Ps[3 * r0], q0y = Ps[3 * r0 + 1], q0z = Ps[3 * r0 + 2];
        const float q1x = Ps[3 * r1], q1y = Ps[3 * r1 + 1], q1z = Ps[3 * r1 + 2];
        const ull m0x = f2_bcast(-2.0f * q0x), m0y = f2_bcast(-2.0f * q0y), m0z = f2_bcast(-2.0f * q0z);
        const ull m1x = f2_bcast(-2.0f * q1x), m1y = f2_bcast(-2.0f * q1y), m1z = f2_bcast(-2.0f * q1z);
        const float q0sq = fmaf(q0x, q0x, fmaf(q0y, q0y, q0z * q0z));
        const float q1sq = fmaf(q1x, q1x, fmaf(q1y, q1y, q1z * q1z));

        float best0 = CUDART_INF_F, best1 = CUDART_INF_F;

#pragma unroll 5
        for (int g = 0; g < IGROUPS; ++g) {
            const float4 aA = sxy[2 * g],     zA = szc[2 * g];
            const float4 aB = sxy[2 * g + 1], zB = szc[2 * g + 1];
            {
                float a0, a1, c0, c1;
                group_dists(aA, zA, aB, zB, m0x, m0y, m0z, a0, a1, c0, c1);
                best0 = fminf(best0, fminf(fminf(a0, a1), fminf(c0, c1)));
            }
            {
                float a0, a1, c0, c1;
                group_dists(aA, zA, aB, zB, m1x, m1y, m1z, a0, a1, c0, c1);
                best1 = fminf(best1, fminf(fminf(a0, a1), fminf(c0, c1)));
            }
        }

        if (v0) g_so_d2[by * M_SIMP + j0] = best0 + q0sq;
        if (v1) g_so_d2[by * M_SIMP + j1] = best1 + q1sq;
    }
}

// ---------------------------------------------------------------------------
// Reduce: 128-thread blocks for more latency streams; shuffle reduction;
// counter-elected last block does fixed-order final sum.
// ---------------------------------------------------------------------------
#define RT 128
#define RB ((N_ORIG + M_SIMP + RT - 1) / RT)   // 313

__global__ __launch_bounds__(RT) void kern_reduce(const float* __restrict__ prob,
                                                  float* __restrict__ out) {
    const int idx = blockIdx.x * RT + threadIdx.x;

    float local = 0.0f;
    if (idx < N_ORIG) {
        float best = g_os_d2[idx];
        int bj = g_os_j[idx];
#pragma unroll
        for (int sp = 1; sp < JSPLIT; ++sp) {
            const float v = g_os_d2[sp * N_ORIG + idx];
            if (v < best) { best = v; bj = g_os_j[sp * N_ORIG + idx]; }
        }
        local = sqrtf(fmaxf(best, 0.0f)) * prob[bj];
    } else if (idx < N_ORIG + M_SIMP) {
        const int j = idx - N_ORIG;
        float best = g_so_d2[j];
#pragma unroll
        for (int sp = 1; sp < ISPLIT; ++sp)
            best = fminf(best, g_so_d2[sp * M_SIMP + j]);
        local = sqrtf(fmaxf(best, 0.0f)) * prob[j];
    }

    // intra-warp fixed-order reduction
#pragma unroll
    for (int off = 16; off > 0; off >>= 1)
        local += __shfl_down_sync(0xFFFFFFFFu, local, off);

    __shared__ float warpsum[RT / 32];
    if ((threadIdx.x & 31) == 0) warpsum[threadIdx.x >> 5] = local;
    __syncthreads();

    __shared__ bool amLast;
    if (threadIdx.x == 0) {
        float s = 0.0f;
#pragma unroll
        for (int w = 0; w < RT / 32; ++w) s += warpsum[w];
        g_part[blockIdx.x] = s;
        __threadfence();
        amLast = (atomicAdd(&g_count, 1) == gridDim.x - 1);
    }
    __syncthreads();

    if (amLast) {
        // fixed-order final sum over RB partials (deterministic)
        float s = 0.0f;
#pragma unroll
        for (int base = 0; base < RB; base += RT) {
            const int p = base + threadIdx.x;
            if (p < RB) s += __ldcg(&g_part[p]);
        }
#pragma unroll
        for (int off = 16; off > 0; off >>= 1)
            s += __shfl_down_sync(0xFFFFFFFFu, s, off);
        if ((threadIdx.x & 31) == 0) warpsum[threadIdx.x >> 5] = s;
        __syncthreads();
        if (threadIdx.x == 0) {
            float t = 0.0f;
#pragma unroll
            for (int w = 0; w < RT / 32; ++w) t += warpsum[w];
            out[0] = t;
            g_count = 0;     // reset for next graph replay
        }
    }
}

extern "C" void kernel_launch(void* const* d_in, const int* in_sizes, int n_in,
                              void* d_out, int out_size) {
    const float* P    = (const float*)d_in[0];   // (N, 3)
    const float* Ps   = (const float*)d_in[1];   // (M, 3)
    const float* prob = (const float*)d_in[2];   // (M,)
    float* out = (float*)d_out;

    kern_main<<<TOTAL_BLOCKS, 256>>>(P, Ps);
    kern_reduce<<<RB, RT>>>(prob, out);
}